// round 2
// baseline (speedup 1.0000x reference)
#include <cuda_runtime.h>
#include <math_constants.h>

#define B     4096
#define D     256
#define NCLS  64
#define BM    128
#define BN    128
#define BK    16
#define MARGIN 0.3f

// Scratch (no device allocation allowed).
__device__ float g_sq[B];
__device__ int   g_hp[B];     // hard-positive, float bits (nonneg -> int order ok)
__device__ int   g_hn[B];     // hard-negative, float bits
__device__ int   g_cnt[NCLS];
__device__ int   g_lab[B];    // canonical int labels

// ---------------------------------------------------------------------------
// Prologue 0: label dtype sniff + canonicalize + histogram. Single block.
// Works whether d_in[1] is int32[4096] or int64[4096]:
//   - Reads first 4096 32-bit words (in-bounds under both layouts).
//   - int64 layout => every odd word is 0 (labels in [0,64));
//     int32 layout => odd words are random labels, virtually never all zero.
// ---------------------------------------------------------------------------
__global__ void label_prep_kernel(const unsigned int* __restrict__ raw) {
    __shared__ int odd_nonzero;
    __shared__ int c[NCLS];
    if (threadIdx.x == 0) odd_nonzero = 0;
    if (threadIdx.x < NCLS) c[threadIdx.x] = 0;
    __syncthreads();
    for (int w = threadIdx.x; w < B; w += blockDim.x)
        if ((w & 1) && raw[w] != 0u) odd_nonzero = 1;
    __syncthreads();
    const bool is32 = (odd_nonzero != 0);
    for (int i = threadIdx.x; i < B; i += blockDim.x) {
        int v = is32 ? (int)raw[i] : (int)raw[2 * i];
        g_lab[i] = v;
        atomicAdd(&c[v & (NCLS - 1)], 1);
    }
    __syncthreads();
    if (threadIdx.x < NCLS) g_cnt[threadIdx.x] = c[threadIdx.x];
}

// ---------------------------------------------------------------------------
// Prologue 1: squared norms + reset per-row scratch. One warp per row.
// ---------------------------------------------------------------------------
__global__ void sq_init_kernel(const float* __restrict__ emb) {
    int warp = (blockIdx.x * blockDim.x + threadIdx.x) >> 5;
    int lane = threadIdx.x & 31;
    if (warp >= B) return;
    const float4* p = (const float4*)(emb + (size_t)warp * D);
    float s = 0.f;
#pragma unroll
    for (int t = 0; t < 2; t++) {
        float4 v = p[lane + t * 32];
        s += v.x * v.x + v.y * v.y + v.z * v.z + v.w * v.w;
    }
#pragma unroll
    for (int o = 16; o > 0; o >>= 1) s += __shfl_xor_sync(0xffffffffu, s, o);
    if (lane == 0) {
        g_sq[warp] = s;
        g_hp[warp] = 0;           // 0.0f bits
        g_hn[warp] = 0x7f800000;  // +inf bits
    }
}

// ---------------------------------------------------------------------------
// Main: fused tiled Gram + distance + masked row max/min.
// 128x128 tile per block, 256 threads, 8x8 per-thread micro-tile, BK=16.
// ---------------------------------------------------------------------------
__global__ __launch_bounds__(256, 2)
void dist_kernel(const float* __restrict__ emb) {
    __shared__ float As[BK][BM + 4];
    __shared__ float Bs[BK][BN + 4];
    __shared__ float sqa[BM], sqb[BN];
    __shared__ int   la[BM], lb[BN];
    __shared__ int   smax[BM], smin[BM];

    const int i0 = blockIdx.y * BM;
    const int j0 = blockIdx.x * BN;
    const int tid = threadIdx.x;

    if (tid < BM) {
        sqa[tid] = g_sq[i0 + tid];
        sqb[tid] = g_sq[j0 + tid];
        la[tid]  = g_lab[i0 + tid];
        lb[tid]  = g_lab[j0 + tid];
        smax[tid] = 0;
        smin[tid] = 0x7f800000;
    }

    const int tx = tid & 15;   // 0..15 -> 8 cols each
    const int ty = tid >> 4;   // 0..15 -> 8 rows each

    float acc[8][8];
#pragma unroll
    for (int m = 0; m < 8; m++)
#pragma unroll
        for (int n = 0; n < 8; n++) acc[m][n] = 0.f;

    // Load mapping: 4 threads per row, each loads one float4 of K.
    const int lrow = tid >> 2;        // 0..63
    const int lk4  = (tid & 3) * 4;   // 0,4,8,12
    const float* Abase = emb + (size_t)(i0 + lrow) * D + lk4;
    const float* Bbase = emb + (size_t)(j0 + lrow) * D + lk4;

    for (int k0 = 0; k0 < D; k0 += BK) {
        __syncthreads();
#pragma unroll
        for (int half = 0; half < 2; half++) {
            float4 va = *(const float4*)(Abase + (size_t)half * 64 * D + k0);
            float4 vb = *(const float4*)(Bbase + (size_t)half * 64 * D + k0);
            int r = lrow + half * 64;
            As[lk4 + 0][r] = va.x; As[lk4 + 1][r] = va.y;
            As[lk4 + 2][r] = va.z; As[lk4 + 3][r] = va.w;
            Bs[lk4 + 0][r] = vb.x; Bs[lk4 + 1][r] = vb.y;
            Bs[lk4 + 2][r] = vb.z; Bs[lk4 + 3][r] = vb.w;
        }
        __syncthreads();
#pragma unroll
        for (int k = 0; k < BK; k++) {
            float a[8], b[8];
#pragma unroll
            for (int m = 0; m < 8; m++) a[m] = As[k][ty * 8 + m];
#pragma unroll
            for (int n = 0; n < 8; n++) b[n] = Bs[k][tx * 8 + n];
#pragma unroll
            for (int m = 0; m < 8; m++)
#pragma unroll
                for (int n = 0; n < 8; n++)
                    acc[m][n] = fmaf(a[m], b[n], acc[m][n]);
        }
    }

    // Epilogue: distances + masked row-wise max/min into shared, then global.
    const int ib = ty * 8, jb = tx * 8;
#pragma unroll
    for (int m = 0; m < 8; m++) {
        const int   i  = i0 + ib + m;
        const int   li = la[ib + m];
        const float si = sqa[ib + m];
        float rmax = -1.0f;
        float rmin = CUDART_INF_F;
#pragma unroll
        for (int n = 0; n < 8; n++) {
            const int j = j0 + jb + n;
            float d2 = si + sqb[jb + n] - 2.0f * acc[m][n];
            float d  = sqrtf(fmaxf(d2, 0.0f));
            bool same = (li == lb[jb + n]);
            if (same) {
                if (i != j) rmax = fmaxf(rmax, d);
            } else {
                rmin = fminf(rmin, d);
            }
        }
        if (rmax >= 0.0f) atomicMax(&smax[ib + m], __float_as_int(rmax));
        if (rmin < CUDART_INF_F) atomicMin(&smin[ib + m], __float_as_int(rmin));
    }
    __syncthreads();
    if (tid < BM) {
        if (smax[tid] > 0)          atomicMax(&g_hp[i0 + tid], smax[tid]);
        if (smin[tid] < 0x7f800000) atomicMin(&g_hn[i0 + tid], smin[tid]);
    }
}

// ---------------------------------------------------------------------------
// Epilogue: mean over valid rows of relu(hp - hn + margin). Single block.
// ---------------------------------------------------------------------------
__global__ void loss_kernel(float* __restrict__ out) {
    __shared__ float ssum[256];
    __shared__ int   scnt[256];
    float sum = 0.f;
    int   cnt = 0;
    for (int i = threadIdx.x; i < B; i += 256) {
        int c = g_cnt[g_lab[i]];
        bool valid = (c > 1) && (c < B);
        if (valid) {
            float hp = __int_as_float(g_hp[i]);
            float hn = __int_as_float(g_hn[i]);
            float l  = hp - hn + MARGIN;
            sum += (l > 0.f) ? l : 0.f;
            cnt += 1;
        }
    }
    ssum[threadIdx.x] = sum;
    scnt[threadIdx.x] = cnt;
    __syncthreads();
    for (int s = 128; s > 0; s >>= 1) {
        if (threadIdx.x < s) {
            ssum[threadIdx.x] += ssum[threadIdx.x + s];
            scnt[threadIdx.x] += scnt[threadIdx.x + s];
        }
        __syncthreads();
    }
    if (threadIdx.x == 0)
        out[0] = (scnt[0] > 0) ? ssum[0] / (float)scnt[0] : 0.0f;
}

// ---------------------------------------------------------------------------
extern "C" void kernel_launch(void* const* d_in, const int* in_sizes, int n_in,
                              void* d_out, int out_size) {
    const float*        emb = (const float*)d_in[0];
    const unsigned int* lab = (const unsigned int*)d_in[1];
    float*              out = (float*)d_out;

    label_prep_kernel<<<1, 256>>>(lab);
    sq_init_kernel<<<(B * 32) / 256, 256>>>(emb);
    dim3 grid(B / BN, B / BM);
    dist_kernel<<<grid, 256>>>(emb);
    loss_kernel<<<1, 256>>>(out);
}

// round 13
// speedup vs baseline: 1.4540x; 1.4540x over previous
#include <cuda_runtime.h>
#include <math_constants.h>

typedef unsigned long long ull;

#define B     4096
#define D     256
#define NCLS  64
#define BM    128
#define BN    128
#define BK    16
#define MARGIN 0.3f

// Scratch (no device allocation allowed).
__device__ float g_sq[B];
__device__ int   g_hp[B];     // hard-positive, float bits (nonneg -> int order ok)
__device__ int   g_hn[B];     // hard-negative, float bits
__device__ int   g_cnt[NCLS];
__device__ int   g_lab[B];    // canonical int labels

// ---- packed f32x2 helpers (sm_103a) ---------------------------------------
__device__ __forceinline__ ull pack_dup(float x) {
    ull r; unsigned xi = __float_as_uint(x);
    asm("mov.b64 %0, {%1, %2};" : "=l"(r) : "r"(xi), "r"(xi));
    return r;
}
__device__ __forceinline__ void unpack2(ull v, float& lo, float& hi) {
    unsigned a, b;
    asm("mov.b64 {%0, %1}, %2;" : "=r"(a), "=r"(b) : "l"(v));
    lo = __uint_as_float(a); hi = __uint_as_float(b);
}
__device__ __forceinline__ ull ffma2(ull a, ull b, ull c) {
    ull d;
    asm("fma.rn.f32x2 %0, %1, %2, %3;" : "=l"(d) : "l"(a), "l"(b), "l"(c));
    return d;
}

// ---------------------------------------------------------------------------
// Prologue (fused): label sniff/canonicalize/histogram (block 0 only) +
// squared norms + per-row scratch reset (warp per row).
// Label buffer may be int32[4096] or int64[4096]; under int64 every odd
// 32-bit word is 0 (labels in [0,64)). First 4096 words are in-bounds
// under both layouts.
// ---------------------------------------------------------------------------
__global__ void prep_kernel(const float* __restrict__ emb,
                            const unsigned int* __restrict__ raw) {
    // squared norms: one warp per row
    int warp = (blockIdx.x * blockDim.x + threadIdx.x) >> 5;
    int lane = threadIdx.x & 31;
    if (warp < B) {
        const float4* p = (const float4*)(emb + (size_t)warp * D);
        float s = 0.f;
#pragma unroll
        for (int t = 0; t < 2; t++) {
            float4 v = p[lane + t * 32];
            s += v.x * v.x + v.y * v.y + v.z * v.z + v.w * v.w;
        }
#pragma unroll
        for (int o = 16; o > 0; o >>= 1) s += __shfl_xor_sync(0xffffffffu, s, o);
        if (lane == 0) {
            g_sq[warp] = s;
            g_hp[warp] = 0;           // 0.0f bits
            g_hn[warp] = 0x7f800000;  // +inf bits
        }
    }
    // labels: block 0 only
    if (blockIdx.x == 0) {
        __shared__ int odd_nonzero;
        __shared__ int c[NCLS];
        if (threadIdx.x == 0) odd_nonzero = 0;
        if (threadIdx.x < NCLS) c[threadIdx.x] = 0;
        __syncthreads();
        for (int w = threadIdx.x; w < B; w += blockDim.x)
            if ((w & 1) && raw[w] != 0u) odd_nonzero = 1;
        __syncthreads();
        const bool is32 = (odd_nonzero != 0);
        for (int i = threadIdx.x; i < B; i += blockDim.x) {
            int v = is32 ? (int)raw[i] : (int)raw[2 * i];
            g_lab[i] = v;
            atomicAdd(&c[v & (NCLS - 1)], 1);
        }
        __syncthreads();
        if (threadIdx.x < NCLS) g_cnt[threadIdx.x] = c[threadIdx.x];
    }
}

// ---------------------------------------------------------------------------
// Main: symmetric fused Gram/distance + masked row & col max/min.
// Only tiles with bi <= bj are computed (bi = blockIdx.y, bj = blockIdx.x).
// Inner loop uses packed fma.rn.f32x2; A operand is stored duplicated in
// shared so FFMA2 operands come straight out of LDS with no repacking.
// ---------------------------------------------------------------------------
__global__ __launch_bounds__(256, 2)
void dist_kernel(const float* __restrict__ emb) {
    const int bi = blockIdx.y, bj = blockIdx.x;
    if (bi > bj) return;                 // symmetry: upper-triangle tiles only
    const bool diag = (bi == bj);

    __shared__ ull   As2[BK][BM + 2];    // duplicated pairs (v,v)
    __shared__ float Bs[BK][BN + 4];
    __shared__ float sqa[BM], sqb[BN];
    __shared__ int   la[BM], lb[BN];
    __shared__ int   smaxA[BM], sminA[BM];   // row anchors (i)
    __shared__ int   smaxB[BN], sminB[BN];   // col anchors (j)

    const int i0 = bi * BM;
    const int j0 = bj * BN;
    const int tid = threadIdx.x;

    if (tid < BM) {
        sqa[tid] = g_sq[i0 + tid];
        sqb[tid] = g_sq[j0 + tid];
        la[tid]  = g_lab[i0 + tid];
        lb[tid]  = g_lab[j0 + tid];
        smaxA[tid] = 0;  sminA[tid] = 0x7f800000;
        smaxB[tid] = 0;  sminB[tid] = 0x7f800000;
    }

    const int tx = tid & 15;   // 0..15 -> 8 cols each
    const int ty = tid >> 4;   // 0..15 -> 8 rows each

    ull acc2[8][4];            // [m][n-pair] packed fp32 pairs
#pragma unroll
    for (int m = 0; m < 8; m++)
#pragma unroll
        for (int n = 0; n < 4; n++) acc2[m][n] = 0ull;

    // Load mapping: 4 threads per row, each loads one float4 of K.
    const int lrow = tid >> 2;        // 0..63
    const int lk4  = (tid & 3) * 4;   // 0,4,8,12
    const float* Abase = emb + (size_t)(i0 + lrow) * D + lk4;
    const float* Bbase = emb + (size_t)(j0 + lrow) * D + lk4;

    for (int k0 = 0; k0 < D; k0 += BK) {
        __syncthreads();
#pragma unroll
        for (int half = 0; half < 2; half++) {
            float4 va = *(const float4*)(Abase + (size_t)half * 64 * D + k0);
            float4 vb = *(const float4*)(Bbase + (size_t)half * 64 * D + k0);
            int r = lrow + half * 64;
            As2[lk4 + 0][r] = pack_dup(va.x);
            As2[lk4 + 1][r] = pack_dup(va.y);
            As2[lk4 + 2][r] = pack_dup(va.z);
            As2[lk4 + 3][r] = pack_dup(va.w);
            Bs[lk4 + 0][r] = vb.x; Bs[lk4 + 1][r] = vb.y;
            Bs[lk4 + 2][r] = vb.z; Bs[lk4 + 3][r] = vb.w;
        }
        __syncthreads();
#pragma unroll
        for (int k = 0; k < BK; k++) {
            const ull* A2 = &As2[k][ty * 8];
            const ull* B2 = (const ull*)&Bs[k][tx * 8];
            ull a2[8], b2[4];
#pragma unroll
            for (int m = 0; m < 8; m++) a2[m] = A2[m];
#pragma unroll
            for (int n = 0; n < 4; n++) b2[n] = B2[n];
#pragma unroll
            for (int m = 0; m < 8; m++)
#pragma unroll
                for (int n = 0; n < 4; n++)
                    acc2[m][n] = ffma2(a2[m], b2[n], acc2[m][n]);
        }
    }

    // Epilogue: distances + masked row-wise AND col-wise max/min.
    const int ib = ty * 8, jb = tx * 8;
    float cmx[8], cmn[8];
#pragma unroll
    for (int n = 0; n < 8; n++) { cmx[n] = -1.0f; cmn[n] = CUDART_INF_F; }

#pragma unroll
    for (int m = 0; m < 8; m++) {
        const int   i  = i0 + ib + m;
        const int   li = la[ib + m];
        const float si = sqa[ib + m];
        float rmx = -1.0f, rmn = CUDART_INF_F;
#pragma unroll
        for (int n2 = 0; n2 < 4; n2++) {
            float p0, p1;
            unpack2(acc2[m][n2], p0, p1);
#pragma unroll
            for (int e = 0; e < 2; e++) {
                const int n = 2 * n2 + e;
                const int j = j0 + jb + n;
                float dot = e ? p1 : p0;
                float d2 = si + sqb[jb + n] - 2.0f * dot;
                float d  = sqrtf(fmaxf(d2, 0.0f));
                bool same = (li == lb[jb + n]);
                if (same) {
                    if (i != j) {
                        rmx = fmaxf(rmx, d);
                        cmx[n] = fmaxf(cmx[n], d);
                    }
                } else {
                    rmn = fminf(rmn, d);
                    cmn[n] = fminf(cmn[n], d);
                }
            }
        }
        if (rmx >= 0.0f)        atomicMax(&smaxA[ib + m], __float_as_int(rmx));
        if (rmn < CUDART_INF_F) atomicMin(&sminA[ib + m], __float_as_int(rmn));
    }
    if (!diag) {
#pragma unroll
        for (int n = 0; n < 8; n++) {
            if (cmx[n] >= 0.0f)        atomicMax(&smaxB[jb + n], __float_as_int(cmx[n]));
            if (cmn[n] < CUDART_INF_F) atomicMin(&sminB[jb + n], __float_as_int(cmn[n]));
        }
    }
    __syncthreads();
    if (tid < BM) {
        if (smaxA[tid] > 0)          atomicMax(&g_hp[i0 + tid], smaxA[tid]);
        if (sminA[tid] < 0x7f800000) atomicMin(&g_hn[i0 + tid], sminA[tid]);
        if (!diag) {
            if (smaxB[tid] > 0)          atomicMax(&g_hp[j0 + tid], smaxB[tid]);
            if (sminB[tid] < 0x7f800000) atomicMin(&g_hn[j0 + tid], sminB[tid]);
        }
    }
}

// ---------------------------------------------------------------------------
// Epilogue: mean over valid rows of relu(hp - hn + margin). Single block.
// ---------------------------------------------------------------------------
__global__ void loss_kernel(float* __restrict__ out) {
    __shared__ float ssum[1024];
    __shared__ int   scnt[1024];
    float sum = 0.f;
    int   cnt = 0;
    for (int i = threadIdx.x; i < B; i += 1024) {
        int c = g_cnt[g_lab[i]];
        bool valid = (c > 1) && (c < B);
        if (valid) {
            float hp = __int_as_float(g_hp[i]);
            float hn = __int_as_float(g_hn[i]);
            float l  = hp - hn + MARGIN;
            sum += (l > 0.f) ? l : 0.f;
            cnt += 1;
        }
    }
    ssum[threadIdx.x] = sum;
    scnt[threadIdx.x] = cnt;
    __syncthreads();
    for (int s = 512; s > 0; s >>= 1) {
        if (threadIdx.x < s) {
            ssum[threadIdx.x] += ssum[threadIdx.x + s];
            scnt[threadIdx.x] += scnt[threadIdx.x + s];
        }
        __syncthreads();
    }
    if (threadIdx.x == 0)
        out[0] = (scnt[0] > 0) ? ssum[0] / (float)scnt[0] : 0.0f;
}

// ---------------------------------------------------------------------------
extern "C" void kernel_launch(void* const* d_in, const int* in_sizes, int n_in,
                              void* d_out, int out_size) {
    const float*        emb = (const float*)d_in[0];
    const unsigned int* lab = (const unsigned int*)d_in[1];
    float*              out = (float*)d_out;

    prep_kernel<<<(B * 32) / 256, 256>>>(emb, lab);
    dim3 grid(B / BN, B / BM);
    dist_kernel<<<grid, 256>>>(emb);
    loss_kernel<<<1, 1024>>>(out);
}